// round 16
// baseline (speedup 1.0000x reference)
#include <cuda_runtime.h>
#include <cuda_bf16.h>
#include <cstdint>

// ============================================================================
// LogMM: out[16384,1024] = log( x[16384,1024] @ matrix[1024,1024] )
// (reference's big/small branches sum exactly to log(max(y,tiny)))
//
// R16: single fused kernel. Phase 1: grid-stride fp32->bf16 conversion of x
// and transpose-conversion of matrix. Phase 2: device-wide generation-ticket
// barrier (grid=296 = 2 CTAs/SM x >=148 SMs, 99KB smem -> all CTAs resident
// -> spin is deadlock-free; monotonic counter needs no reset across graph
// replays). Phase 3: champion GEMM mainloop (byte-identical to R14/R15):
// persistent chunk streaming, 128x128 tile, BK=64, 3-stage cp.async,
// .cs streaming output stores.
// ============================================================================

#define M_TOTAL 16384
#define N_TOTAL 1024
#define K_TOTAL 1024
#define TILE_M 128
#define TILE_N 128
#define BK 64                    // bf16 per K-chunk (128 B per row)
#define NCHUNK (K_TOTAL / BK)    // 16
#define NSTAGE 3
#define NTILES ((M_TOTAL / TILE_M) * (N_TOTAL / TILE_N))  // 1024
#define GRID_GEMM 296            // 2 CTAs/SM x 148 SMs (min capacity: all resident)
#define NTHREADS 256

static constexpr int SMEM_TILES = 1024;
static constexpr int TILE_BYTES = TILE_M * 128;     // 16384
static constexpr int BUF_STRIDE = 2 * TILE_BYTES;   // 32768
static constexpr int SMEM_TOTAL = SMEM_TILES + NSTAGE * BUF_STRIDE;  // 99328

// Scratch bf16 buffers + monotonic barrier counter (device globals)
__device__ __align__(256) __nv_bfloat16 g_xb[(size_t)M_TOTAL * K_TOTAL];
__device__ __align__(256) __nv_bfloat16 g_bt[(size_t)N_TOTAL * K_TOTAL];
__device__ unsigned int g_bar;   // zero-init; monotonic across graph replays

// ---------------------------------------------------------------------------
// Helpers
// ---------------------------------------------------------------------------
__device__ __forceinline__ uint32_t smem_u32(const void* p) {
    uint32_t a;
    asm("{ .reg .u64 t; cvta.to.shared.u64 t, %1; cvt.u32.u64 %0, t; }" : "=r"(a) : "l"(p));
    return a;
}
__device__ __forceinline__ uint32_t sw128(uint32_t off) {
    return off ^ ((off >> 3) & 0x70);
}
__device__ __forceinline__ void cp_async16(uint32_t smem_addr, const void* gptr) {
    asm volatile("cp.async.cg.shared.global [%0], [%1], 16;"
                 :: "r"(smem_addr), "l"(gptr) : "memory");
}
#define CP_COMMIT() asm volatile("cp.async.commit_group;" ::: "memory")
#define CP_WAIT(n)  asm volatile("cp.async.wait_group %0;" :: "n"(n) : "memory")

__device__ __forceinline__ void ldsm_x4(uint32_t* r, uint32_t addr) {
    asm volatile("ldmatrix.sync.aligned.m8n8.x4.shared.b16 {%0, %1, %2, %3}, [%4];"
                 : "=r"(r[0]), "=r"(r[1]), "=r"(r[2]), "=r"(r[3]) : "r"(addr));
}
__device__ __forceinline__ void mma16816(float* c, const uint32_t* a, const uint32_t* b) {
    asm volatile("mma.sync.aligned.m16n8k16.row.col.f32.bf16.bf16.f32 "
                 "{%0, %1, %2, %3}, {%4, %5, %6, %7}, {%8, %9}, {%0, %1, %2, %3};"
                 : "+f"(c[0]), "+f"(c[1]), "+f"(c[2]), "+f"(c[3])
                 : "r"(a[0]), "r"(a[1]), "r"(a[2]), "r"(a[3]), "r"(b[0]), "r"(b[1]));
}
__device__ __forceinline__ uint32_t pack_bf16x2(float a, float b) {
    __nv_bfloat162 h = __floats2bfloat162_rn(a, b);
    return *reinterpret_cast<uint32_t*>(&h);
}
__device__ __forceinline__ void stg_cs_f2(float* p, float2 v) {
    asm volatile("st.global.cs.v2.f32 [%0], {%1, %2};"
                 :: "l"(p), "f"(v.x), "f"(v.y) : "memory");
}
__device__ __forceinline__ float4 ldg_cs_f4(const float* p) {
    float4 v;
    asm volatile("ld.global.cs.v4.f32 {%0, %1, %2, %3}, [%4];"
                 : "=f"(v.x), "=f"(v.y), "=f"(v.z), "=f"(v.w) : "l"(p));
    return v;
}
__device__ __forceinline__ float ldg_cs_f(const float* p) {
    float v;
    asm volatile("ld.global.cs.f32 %0, [%1];" : "=f"(v) : "l"(p));
    return v;
}

// ---------------------------------------------------------------------------
// GEMM chunk loader (champion): tile = first + (g>>4)*GRID, kc = g&15
// ---------------------------------------------------------------------------
__device__ __forceinline__ void issue_chunk(uint32_t smem_base, int g, int first, int tid) {
    int t = first + (g >> 4) * GRID_GEMM;
    int kc = g & (NCHUNK - 1);
    int m0 = (t >> 3) * TILE_M;
    int n0 = (t & 7) * TILE_N;
    const uint4* Ag = reinterpret_cast<const uint4*>(g_xb + (size_t)m0 * K_TOTAL + kc * BK);
    const uint4* Bg = reinterpret_cast<const uint4*>(g_bt + (size_t)n0 * K_TOTAL + kc * BK);
    uint32_t Abase = smem_base + SMEM_TILES + (g % NSTAGE) * BUF_STRIDE;
    uint32_t Bbase = Abase + TILE_BYTES;
#pragma unroll
    for (int i = 0; i < 4; i++) {
        int cc = i * 256 + tid;           // 1024 16B-chunks per tile
        int row = cc >> 3;                // 0..127
        int c16 = cc & 7;                 // 16B chunk within 128B row
        uint32_t sw = sw128((uint32_t)(row * 128 + c16 * 16));
        cp_async16(Abase + sw, Ag + (size_t)row * (K_TOTAL / 8) + c16);
        cp_async16(Bbase + sw, Bg + (size_t)row * (K_TOTAL / 8) + c16);
    }
    CP_COMMIT();
}

// ---------------------------------------------------------------------------
// Fused kernel: convert -> device barrier -> GEMM+log
// ---------------------------------------------------------------------------
#define X_UNITS (M_TOTAL * K_TOTAL / 8)          // 2097152 8-elem units
#define MT_TILES ((K_TOTAL / 32) * (N_TOTAL / 32))  // 1024

__global__ void __launch_bounds__(NTHREADS, 2)
logmm_fused_kernel(const float* __restrict__ x, const float* __restrict__ mat,
                   float* __restrict__ out) {
    extern __shared__ char smem[];
    uint32_t sb = smem_u32(smem);
    int tid = threadIdx.x;
    int wid = tid >> 5;
    int lid = tid & 31;
    int bid = blockIdx.x;

    // ---------------- Phase 1a: x fp32 -> bf16 (grid-stride) ----------------
    for (int u = bid * NTHREADS + tid; u < X_UNITS; u += GRID_GEMM * NTHREADS) {
        size_t i = (size_t)u * 8;
        float4 a = ldg_cs_f4(x + i);
        float4 b = ldg_cs_f4(x + i + 4);
        uint4 o;
        o.x = pack_bf16x2(a.x, a.y);
        o.y = pack_bf16x2(a.z, a.w);
        o.z = pack_bf16x2(b.x, b.y);
        o.w = pack_bf16x2(b.z, b.w);
        *reinterpret_cast<uint4*>(g_xb + i) = o;
    }

    // ---------------- Phase 1b: matrix[K,N] -> Bt[N,K] bf16 -----------------
    {
        float* tile = reinterpret_cast<float*>(smem);   // 32x33 floats (4224 B)
        int lane = tid & 31;
        int rr = tid >> 5;               // 0..7
        for (int t = bid; t < MT_TILES; t += GRID_GEMM) {
            int bn = (t & 31) * 32;      // n block
            int bk = (t >> 5) * 32;      // k block
            __syncthreads();             // protect smem reuse across iterations
#pragma unroll
            for (int i = 0; i < 4; i++) {
                int row = i * 8 + rr;    // k within tile
                tile[row * 33 + lane] = ldg_cs_f(mat + (size_t)(bk + row) * N_TOTAL + bn + lane);
            }
            __syncthreads();
#pragma unroll
            for (int i = 0; i < 4; i++) {
                int row = i * 8 + rr;    // n within tile
                g_bt[(size_t)(bn + row) * K_TOTAL + bk + lane] =
                    __float2bfloat16_rn(tile[lane * 33 + row]);
            }
        }
    }

    // ---------------- Phase 2: device-wide generation barrier ----------------
    // All GRID_GEMM CTAs are co-resident (2/SM on >=148 SMs) -> spin is safe.
    // Monotonic counter: gen = ticket/GRID; wait for (gen+1)*GRID. No reset
    // needed across graph replays (stream-ordered launches keep gens disjoint).
    __threadfence();                     // release conversions
    __syncthreads();
    if (tid == 0) {
        unsigned int ticket = atomicAdd(&g_bar, 1u);
        unsigned int target = (ticket / GRID_GEMM + 1u) * GRID_GEMM;
        unsigned int cur;
        do {
            asm volatile("ld.global.cg.u32 %0, [%1];" : "=r"(cur) : "l"(&g_bar));
            if (cur < target) __nanosleep(128);
        } while (cur < target);
    }
    __syncthreads();
    __threadfence();                     // acquire conversions

    // ---------------- Phase 3: champion GEMM + log ---------------------------
    int warp_m = wid >> 2;               // 8 warps: 2x4, warp tile 64x32
    int warp_n = wid & 3;

    int first = bid;
    int my_tiles = (NTILES - 1 - first) / GRID_GEMM + 1;  // 3 or 4
    int G = my_tiles * NCHUNK;

    float acc[4][4][4];
#pragma unroll
    for (int mf = 0; mf < 4; mf++)
#pragma unroll
        for (int nf = 0; nf < 4; nf++)
#pragma unroll
            for (int i = 0; i < 4; i++) acc[mf][nf][i] = 0.0f;

    // Prologue: fill 2 of 3 stages
    issue_chunk(sb, 0, first, tid);
    issue_chunk(sb, 1, first, tid);

    for (int g = 0; g < G; g++) {
        if (g == G - 1) { CP_WAIT(0); } else { CP_WAIT(1); }
        __syncthreads();

        // Prefetch chunk g+2 (may belong to the NEXT tile -> no drain)
        if (g + 2 < G) issue_chunk(sb, g + 2, first, tid);

        uint32_t Ab = sb + SMEM_TILES + (g % NSTAGE) * BUF_STRIDE;
        uint32_t Bb = Ab + TILE_BYTES;
#pragma unroll
        for (int ks = 0; ks < 4; ks++) {
            uint32_t a[4][4], b[2][4];
#pragma unroll
            for (int mf = 0; mf < 4; mf++) {
                int row = warp_m * 64 + mf * 16 + (lid & 15);
                uint32_t off = (uint32_t)(row * 128 + ks * 32 + ((lid >> 4) << 4));
                ldsm_x4(a[mf], Ab + sw128(off));
            }
#pragma unroll
            for (int p = 0; p < 2; p++) {
                int row = warp_n * 32 + p * 16 + (lid & 7) + ((lid >> 4) << 3);
                uint32_t off = (uint32_t)(row * 128 + ks * 32 + (((lid >> 3) & 1) << 4));
                ldsm_x4(b[p], Bb + sw128(off));
            }
#pragma unroll
            for (int mf = 0; mf < 4; mf++)
#pragma unroll
                for (int nf = 0; nf < 4; nf++)
                    mma16816(acc[mf][nf], a[mf], b[nf >> 1] + (nf & 1) * 2);
        }

        // Tile finished? Epilogue overlapped with in-flight next-tile loads.
        if ((g & (NCHUNK - 1)) == NCHUNK - 1) {
            int t = first + (g >> 4) * GRID_GEMM;
            int m0 = (t >> 3) * TILE_M;
            int n0 = (t & 7) * TILE_N;
#pragma unroll
            for (int mf = 0; mf < 4; mf++) {
#pragma unroll
                for (int nf = 0; nf < 4; nf++) {
                    int row0 = m0 + warp_m * 64 + mf * 16 + (lid >> 2);
                    int col = n0 + warp_n * 32 + nf * 8 + (lid & 3) * 2;
                    float2 v0, v1;
                    v0.x = __logf(fmaxf(acc[mf][nf][0], 1.17549435e-38f));
                    v0.y = __logf(fmaxf(acc[mf][nf][1], 1.17549435e-38f));
                    v1.x = __logf(fmaxf(acc[mf][nf][2], 1.17549435e-38f));
                    v1.y = __logf(fmaxf(acc[mf][nf][3], 1.17549435e-38f));
                    stg_cs_f2(out + (size_t)row0 * N_TOTAL + col, v0);
                    stg_cs_f2(out + (size_t)(row0 + 8) * N_TOTAL + col, v1);
                    acc[mf][nf][0] = 0.0f;
                    acc[mf][nf][1] = 0.0f;
                    acc[mf][nf][2] = 0.0f;
                    acc[mf][nf][3] = 0.0f;
                }
            }
        }
    }
}

// ---------------------------------------------------------------------------
// Launch
// ---------------------------------------------------------------------------
extern "C" void kernel_launch(void* const* d_in, const int* in_sizes, int n_in,
                              void* d_out, int out_size) {
    const float* x = (const float*)d_in[0];
    const float* mat = (const float*)d_in[1];
    if (n_in >= 2 && in_sizes[0] == N_TOTAL * K_TOTAL && in_sizes[1] == M_TOTAL * K_TOTAL) {
        const float* t = x; x = mat; mat = t;
    }
    float* out = (float*)d_out;

    cudaFuncSetAttribute(logmm_fused_kernel,
                         cudaFuncAttributeMaxDynamicSharedMemorySize, SMEM_TOTAL);

    logmm_fused_kernel<<<GRID_GEMM, NTHREADS, SMEM_TOTAL>>>(x, mat, out);
}

// round 17
// speedup vs baseline: 1.1018x; 1.1018x over previous
#include <cuda_runtime.h>
#include <cuda_bf16.h>
#include <cstdint>

// ============================================================================
// LogMM: out[16384,1024] = log( x[16384,1024] @ matrix[1024,1024] )
// (reference's big/small branches sum exactly to log(max(y,tiny)))
//
// R17: revert R16 fusion (conversion at persistent-GEMM occupancy lost its
// MLP: 5078 -> ~1000 GB/s; -10us). Champion two-kernel structure (R15,
// 100.8us) with one delta: cvt x-path does 16 floats/thread (4 independent
// .cs float4 loads) to raise DRAM efficiency from 63.5%.
// GEMM mainloop byte-identical to champion: persistent chunk streaming,
// 128x128 tile, BK=64, 3-stage cp.async, 2 CTAs/SM (RF-full: 512thr x 123reg),
// .cs streaming epilogue stores.
// ============================================================================

#define M_TOTAL 16384
#define N_TOTAL 1024
#define K_TOTAL 1024
#define TILE_M 128
#define TILE_N 128
#define BK 64                    // bf16 per K-chunk (128 B per row)
#define NCHUNK (K_TOTAL / BK)    // 16
#define NSTAGE 3
#define NTILES ((M_TOTAL / TILE_M) * (N_TOTAL / TILE_N))  // 1024
#define GRID_GEMM 304            // 2 CTAs/SM x 152 SMs

static constexpr int SMEM_TILES = 1024;
static constexpr int TILE_BYTES = TILE_M * 128;     // 16384
static constexpr int BUF_STRIDE = 2 * TILE_BYTES;   // 32768
static constexpr int SMEM_TOTAL = SMEM_TILES + NSTAGE * BUF_STRIDE;  // 99328

// Scratch bf16 buffers (device globals: allocation-free)
__device__ __align__(256) __nv_bfloat16 g_xb[(size_t)M_TOTAL * K_TOTAL];
__device__ __align__(256) __nv_bfloat16 g_bt[(size_t)N_TOTAL * K_TOTAL];

// ---------------------------------------------------------------------------
// Helpers
// ---------------------------------------------------------------------------
__device__ __forceinline__ uint32_t smem_u32(const void* p) {
    uint32_t a;
    asm("{ .reg .u64 t; cvta.to.shared.u64 t, %1; cvt.u32.u64 %0, t; }" : "=r"(a) : "l"(p));
    return a;
}
__device__ __forceinline__ uint32_t sw128(uint32_t off) {
    return off ^ ((off >> 3) & 0x70);
}
__device__ __forceinline__ void cp_async16(uint32_t smem_addr, const void* gptr) {
    asm volatile("cp.async.cg.shared.global [%0], [%1], 16;"
                 :: "r"(smem_addr), "l"(gptr) : "memory");
}
#define CP_COMMIT() asm volatile("cp.async.commit_group;" ::: "memory")
#define CP_WAIT(n)  asm volatile("cp.async.wait_group %0;" :: "n"(n) : "memory")

__device__ __forceinline__ void ldsm_x4(uint32_t* r, uint32_t addr) {
    asm volatile("ldmatrix.sync.aligned.m8n8.x4.shared.b16 {%0, %1, %2, %3}, [%4];"
                 : "=r"(r[0]), "=r"(r[1]), "=r"(r[2]), "=r"(r[3]) : "r"(addr));
}
__device__ __forceinline__ void mma16816(float* c, const uint32_t* a, const uint32_t* b) {
    asm volatile("mma.sync.aligned.m16n8k16.row.col.f32.bf16.bf16.f32 "
                 "{%0, %1, %2, %3}, {%4, %5, %6, %7}, {%8, %9}, {%0, %1, %2, %3};"
                 : "+f"(c[0]), "+f"(c[1]), "+f"(c[2]), "+f"(c[3])
                 : "r"(a[0]), "r"(a[1]), "r"(a[2]), "r"(a[3]), "r"(b[0]), "r"(b[1]));
}
__device__ __forceinline__ uint32_t pack_bf16x2(float a, float b) {
    __nv_bfloat162 h = __floats2bfloat162_rn(a, b);
    return *reinterpret_cast<uint32_t*>(&h);
}
__device__ __forceinline__ void stg_cs_f2(float* p, float2 v) {
    asm volatile("st.global.cs.v2.f32 [%0], {%1, %2};"
                 :: "l"(p), "f"(v.x), "f"(v.y) : "memory");
}
__device__ __forceinline__ float4 ldg_cs_f4(const float* p) {
    float4 v;
    asm volatile("ld.global.cs.v4.f32 {%0, %1, %2, %3}, [%4];"
                 : "=f"(v.x), "=f"(v.y), "=f"(v.z), "=f"(v.w) : "l"(p));
    return v;
}
__device__ __forceinline__ float ldg_cs_f(const float* p) {
    float v;
    asm volatile("ld.global.cs.f32 %0, [%1];" : "=f"(v) : "l"(p));
    return v;
}

// ---------------------------------------------------------------------------
// Fused conversion kernel (single launch):
//   blocks [0, 4096):         x fp32 -> g_xb bf16 (16 elems/thread, 4x MLP)
//   blocks [4096, 4096+1024): matrix[K,N] -> g_bt[N,K] bf16 (32x32 tiles)
// ---------------------------------------------------------------------------
#define CVT_X_BLOCKS (M_TOTAL * K_TOTAL / (256 * 16))  // 4096
#define CVT_T_BLOCKS ((K_TOTAL / 32) * (N_TOTAL / 32)) // 1024

__global__ void __launch_bounds__(256)
cvt_kernel(const float* __restrict__ x, const float* __restrict__ m) {
    int tid = threadIdx.x;
    if (blockIdx.x < CVT_X_BLOCKS) {
        size_t i = ((size_t)blockIdx.x * 256 + tid) * 16;
        // 4 independent streaming loads in flight before any packing
        float4 a0 = ldg_cs_f4(x + i);
        float4 a1 = ldg_cs_f4(x + i + 4);
        float4 a2 = ldg_cs_f4(x + i + 8);
        float4 a3 = ldg_cs_f4(x + i + 12);
        uint4 o0, o1;
        o0.x = pack_bf16x2(a0.x, a0.y);
        o0.y = pack_bf16x2(a0.z, a0.w);
        o0.z = pack_bf16x2(a1.x, a1.y);
        o0.w = pack_bf16x2(a1.z, a1.w);
        o1.x = pack_bf16x2(a2.x, a2.y);
        o1.y = pack_bf16x2(a2.z, a2.w);
        o1.z = pack_bf16x2(a3.x, a3.y);
        o1.w = pack_bf16x2(a3.z, a3.w);
        *reinterpret_cast<uint4*>(g_xb + i) = o0;
        *reinterpret_cast<uint4*>(g_xb + i + 8) = o1;
    } else {
        __shared__ float tile[32][33];
        int t = blockIdx.x - CVT_X_BLOCKS;
        int bn = (t & 31) * 32;          // n block
        int bk = (t >> 5) * 32;          // k block
        int lane = tid & 31;
        int rr = tid >> 5;               // 0..7
#pragma unroll
        for (int i = 0; i < 4; i++) {
            int row = i * 8 + rr;        // k within tile
            tile[row][lane] = ldg_cs_f(m + (size_t)(bk + row) * N_TOTAL + bn + lane);
        }
        __syncthreads();
#pragma unroll
        for (int i = 0; i < 4; i++) {
            int row = i * 8 + rr;        // n within tile
            g_bt[(size_t)(bn + row) * K_TOTAL + bk + lane] =
                __float2bfloat16_rn(tile[lane][row]);
        }
    }
}

// ---------------------------------------------------------------------------
// GEMM + log kernel (persistent, cross-tile pipelined — champion mainloop)
// ---------------------------------------------------------------------------
// Issue cp.asyncs for global chunk g (tile = first + (g>>4)*GRID, kc = g&15)
__device__ __forceinline__ void issue_chunk(uint32_t smem_base, int g, int first, int tid) {
    int t = first + (g >> 4) * GRID_GEMM;
    int kc = g & (NCHUNK - 1);
    int m0 = (t >> 3) * TILE_M;
    int n0 = (t & 7) * TILE_N;
    const uint4* Ag = reinterpret_cast<const uint4*>(g_xb + (size_t)m0 * K_TOTAL + kc * BK);
    const uint4* Bg = reinterpret_cast<const uint4*>(g_bt + (size_t)n0 * K_TOTAL + kc * BK);
    uint32_t Abase = smem_base + SMEM_TILES + (g % NSTAGE) * BUF_STRIDE;
    uint32_t Bbase = Abase + TILE_BYTES;
#pragma unroll
    for (int i = 0; i < 4; i++) {
        int cc = i * 256 + tid;           // 1024 16B-chunks per tile
        int row = cc >> 3;                // 0..127
        int c16 = cc & 7;                 // 16B chunk within 128B row
        uint32_t sw = sw128((uint32_t)(row * 128 + c16 * 16));
        cp_async16(Abase + sw, Ag + (size_t)row * (K_TOTAL / 8) + c16);
        cp_async16(Bbase + sw, Bg + (size_t)row * (K_TOTAL / 8) + c16);
    }
    CP_COMMIT();
}

__global__ void __launch_bounds__(256, 2)
logmm_gemm_kernel(float* __restrict__ out) {
    extern __shared__ char smem[];
    uint32_t sb = smem_u32(smem);
    int tid = threadIdx.x;
    int wid = tid >> 5;
    int lid = tid & 31;

    // 8 warps: warp_m in {0,1} (64 rows), warp_n in {0..3} (32 cols)
    int warp_m = wid >> 2;
    int warp_n = wid & 3;

    int first = blockIdx.x;
    int my_tiles = (NTILES - 1 - first) / GRID_GEMM + 1;  // 4 (first 112) or 3
    int G = my_tiles * NCHUNK;

    float acc[4][4][4];
#pragma unroll
    for (int mf = 0; mf < 4; mf++)
#pragma unroll
        for (int nf = 0; nf < 4; nf++)
#pragma unroll
            for (int i = 0; i < 4; i++) acc[mf][nf][i] = 0.0f;

    // Prologue: fill 2 of 3 stages
    issue_chunk(sb, 0, first, tid);
    issue_chunk(sb, 1, first, tid);

    for (int g = 0; g < G; g++) {
        if (g == G - 1) { CP_WAIT(0); } else { CP_WAIT(1); }
        __syncthreads();

        // Prefetch chunk g+2 (may belong to the NEXT tile -> no drain)
        if (g + 2 < G) issue_chunk(sb, g + 2, first, tid);

        uint32_t Ab = sb + SMEM_TILES + (g % NSTAGE) * BUF_STRIDE;
        uint32_t Bb = Ab + TILE_BYTES;
#pragma unroll
        for (int ks = 0; ks < 4; ks++) {
            uint32_t a[4][4], b[2][4];
#pragma unroll
            for (int mf = 0; mf < 4; mf++) {
                int row = warp_m * 64 + mf * 16 + (lid & 15);
                uint32_t off = (uint32_t)(row * 128 + ks * 32 + ((lid >> 4) << 4));
                ldsm_x4(a[mf], Ab + sw128(off));
            }
#pragma unroll
            for (int p = 0; p < 2; p++) {
                int row = warp_n * 32 + p * 16 + (lid & 7) + ((lid >> 4) << 3);
                uint32_t off = (uint32_t)(row * 128 + ks * 32 + (((lid >> 3) & 1) << 4));
                ldsm_x4(b[p], Bb + sw128(off));
            }
#pragma unroll
            for (int mf = 0; mf < 4; mf++)
#pragma unroll
                for (int nf = 0; nf < 4; nf++)
                    mma16816(acc[mf][nf], a[mf], b[nf >> 1] + (nf & 1) * 2);
        }

        // Tile finished? Epilogue overlapped with in-flight next-tile loads.
        if ((g & (NCHUNK - 1)) == NCHUNK - 1) {
            int t = first + (g >> 4) * GRID_GEMM;
            int m0 = (t >> 3) * TILE_M;
            int n0 = (t & 7) * TILE_N;
#pragma unroll
            for (int mf = 0; mf < 4; mf++) {
#pragma unroll
                for (int nf = 0; nf < 4; nf++) {
                    int row0 = m0 + warp_m * 64 + mf * 16 + (lid >> 2);
                    int col = n0 + warp_n * 32 + nf * 8 + (lid & 3) * 2;
                    float2 v0, v1;
                    v0.x = __logf(fmaxf(acc[mf][nf][0], 1.17549435e-38f));
                    v0.y = __logf(fmaxf(acc[mf][nf][1], 1.17549435e-38f));
                    v1.x = __logf(fmaxf(acc[mf][nf][2], 1.17549435e-38f));
                    v1.y = __logf(fmaxf(acc[mf][nf][3], 1.17549435e-38f));
                    stg_cs_f2(out + (size_t)row0 * N_TOTAL + col, v0);
                    stg_cs_f2(out + (size_t)(row0 + 8) * N_TOTAL + col, v1);
                    acc[mf][nf][0] = 0.0f;
                    acc[mf][nf][1] = 0.0f;
                    acc[mf][nf][2] = 0.0f;
                    acc[mf][nf][3] = 0.0f;
                }
            }
        }
    }
}

// ---------------------------------------------------------------------------
// Launch
// ---------------------------------------------------------------------------
extern "C" void kernel_launch(void* const* d_in, const int* in_sizes, int n_in,
                              void* d_out, int out_size) {
    const float* x = (const float*)d_in[0];
    const float* mat = (const float*)d_in[1];
    if (n_in >= 2 && in_sizes[0] == N_TOTAL * K_TOTAL && in_sizes[1] == M_TOTAL * K_TOTAL) {
        const float* t = x; x = mat; mat = t;
    }
    float* out = (float*)d_out;

    cudaFuncSetAttribute(logmm_gemm_kernel,
                         cudaFuncAttributeMaxDynamicSharedMemorySize, SMEM_TOTAL);

    cvt_kernel<<<CVT_X_BLOCKS + CVT_T_BLOCKS, 256>>>(x, mat);
    logmm_gemm_kernel<<<GRID_GEMM, 256, SMEM_TOTAL>>>(out);
}